// round 2
// baseline (speedup 1.0000x reference)
#include <cuda_runtime.h>
#include <math.h>

#define Nn   4
#define MA   256
#define NFS  128
#define KK   8
#define HID  256
#define OUTD 32
#define RCf  5.0f
#define PIf  3.14159265358979323846f
#define ROWS (Nn*MA)   // 1024 atoms total
#define W2PAD 260      // padded row stride (floats) for transposed Wp2 in smem

// ---------------- scratch (device globals; no allocation allowed) ----------
__device__ float g_a[ROWS];              // h . Wa[:128]
__device__ float g_b[ROWS];              // h . Wa[128:]
__device__ float g_p[ROWS*HID];          // h @ Wp1[:128,:]
__device__ float g_q[ROWS*HID];          // h @ Wp1[128:,:]

// ---------------- kernel A: per-atom projections (+ output prefix) ---------
// grid = ROWS/8 blocks, 256 threads. Each block: 8 atom rows.
__global__ void kA(const float* __restrict__ h,
                   const float* __restrict__ Wp1,
                   const float* __restrict__ Wa,
                   const int*   __restrict__ z,
                   const float* __restrict__ r,
                   float* __restrict__ out, int has_prefix) {
    __shared__ float hs[8*NFS];
    const int t = threadIdx.x;
    const int row0 = blockIdx.x * 8;
    for (int i = t; i < 8*NFS; i += 256) hs[i] = h[(size_t)row0*NFS + i];

    // output prefix (z as float, then r) — independent work, no sync needed
    if (has_prefix) {
        const int gt = blockIdx.x * 256 + t;
        if (gt < ROWS)   out[gt] = (float)z[gt];
        if (gt < ROWS*3) out[ROWS + gt] = r[gt];
    }
    __syncthreads();

    float accp[8], accq[8];
#pragma unroll
    for (int rr = 0; rr < 8; rr++) { accp[rr] = 0.f; accq[rr] = 0.f; }

#pragma unroll 4
    for (int f = 0; f < NFS; f++) {
        const float wt = Wp1[f*HID + t];
        const float wb = Wp1[(NFS+f)*HID + t];
#pragma unroll
        for (int rr = 0; rr < 8; rr++) {
            const float hv = hs[rr*NFS + f];
            accp[rr] = fmaf(hv, wt, accp[rr]);
            accq[rr] = fmaf(hv, wb, accq[rr]);
        }
    }
#pragma unroll
    for (int rr = 0; rr < 8; rr++) {
        g_p[(size_t)(row0+rr)*HID + t] = accp[rr];
        g_q[(size_t)(row0+rr)*HID + t] = accq[rr];
    }

    // a,b: warp w handles atom row w
    const int w = t >> 5, lane = t & 31;
    float sa = 0.f, sb_ = 0.f;
    for (int f = lane; f < NFS; f += 32) {
        const float hv = hs[w*NFS + f];
        sa  = fmaf(hv, Wa[f],     sa);
        sb_ = fmaf(hv, Wa[NFS+f], sb_);
    }
#pragma unroll
    for (int off = 16; off; off >>= 1) {
        sa  += __shfl_down_sync(0xffffffffu, sa,  off);
        sb_ += __shfl_down_sync(0xffffffffu, sb_, off);
    }
    if (lane == 0) { g_a[row0+w] = sa; g_b[row0+w] = sb_; }
}

// ---------------- kernel F: fused attention + topK + MLP + output ----------
// grid = 256 blocks; block = 256 threads; each block handles 4 rows (same n).
__global__ void kF(const int*   __restrict__ z,
                   const float* __restrict__ r,
                   const float* __restrict__ ba_,
                   const float* __restrict__ bp1,
                   const float* __restrict__ Wp2,
                   const float* __restrict__ bp2,
                   float*       __restrict__ cout) {
    __shared__ float w2t[OUTD*W2PAD];                 // transposed Wp2 (padded)
    __shared__ float px[MA], py[MA], pz[MA];
    __shared__ float sbv[MA];
    __shared__ unsigned char smk[MA];
    __shared__ unsigned long long scand[64];          // per-warp top-8 candidates
    __shared__ float wsum[8];
    __shared__ __align__(16) float hid[KK][HID];
    __shared__ float satt[KK];
    __shared__ int   sidx[KK];
    __shared__ float sdx[KK], sdy[KK], sdz[KK];

    const int t   = threadIdx.x;
    const int n   = blockIdx.x >> 6;                  // 64 blocks per molecule
    const int i0  = (blockIdx.x & 63) * 4;
    const int bse = n * MA;

    // molecule-wide loads (once per block)
    px[t]  = r[(size_t)(bse+t)*3 + 0];
    py[t]  = r[(size_t)(bse+t)*3 + 1];
    pz[t]  = r[(size_t)(bse+t)*3 + 2];
    smk[t] = (z[bse+t] > -1) ? 1 : 0;
    sbv[t] = g_b[bse+t];
    // transpose Wp2 [HID,OUTD] -> w2t[o*W2PAD + tt]
    for (int u = t; u < HID*OUTD; u += 256) {
        const int tt = u >> 5, o = u & 31;
        w2t[o*W2PAD + tt] = Wp2[u];
    }
    const float b1  = bp1[t];
    const float bav = ba_[0];
    __syncthreads();

    for (int ir = 0; ir < 4; ir++) {
        const int i   = i0 + ir;
        const int row = bse + i;
        const int j   = t;

        // ---- attention score ----
        const float dx = px[j]-px[i], dy = py[j]-py[i], dz = pz[j]-pz[i];
        const float d  = sqrtf(dx*dx + dy*dy + dz*dz);
        const bool  msk = smk[i] && smk[j] && (j != i);
        float g = 0.f;
        if (msk) {
            const float cf = 0.5f * (cosf(PIf * fminf(d, RCf) / RCf) + 1.f);
            g = expf(g_a[row] + cf*sbv[j] + bav);
        }

        // ---- block sum of g (warp shuffle + tiny shared) ----
        float s = g;
#pragma unroll
        for (int off = 16; off; off >>= 1) s += __shfl_xor_sync(0xffffffffu, s, off);
        if ((t & 31) == 0) wsum[t >> 5] = s;

        // ---- intra-warp exact full rank (butterfly) on unique u64 keys ----
        const unsigned long long key =
            (((unsigned long long)__float_as_uint(g)) << 32) | (unsigned)(MA-1-j);
        int rk = 0;
#pragma unroll
        for (int sft = 1; sft < 32; sft++) {
            const unsigned long long ok = __shfl_xor_sync(0xffffffffu, key, sft);
            rk += (ok > key);
        }
        if (rk < KK) scand[(t >> 5)*KK + rk] = key;
        __syncthreads();

        float sumg = 0.f;
#pragma unroll
        for (int w = 0; w < 8; w++) sumg += wsum[w];
        const float invsum = 1.f / fmaxf(sumg, 1e-8f);

        // ---- warp 0: rank the 64 candidates, emit global top-8 ----
        if (t < 32) {
            const unsigned long long k0 = scand[t], k1 = scand[t + 32];
            int r0 = 0, r1 = 0;
#pragma unroll 8
            for (int m = 0; m < 64; m++) {
                const unsigned long long km = scand[m];
                r0 += (km > k0);
                r1 += (km > k1);
            }
#pragma unroll
            for (int pick = 0; pick < 2; pick++) {
                const unsigned long long kk = pick ? k1 : k0;
                const int rr = pick ? r1 : r0;
                if (rr < KK) {
                    const int jw = MA - 1 - (int)(kk & 0xffffffffu);
                    satt[rr] = __uint_as_float((unsigned)(kk >> 32)) * invsum;
                    sidx[rr] = jw;
                    const float ddx = px[jw]-px[i], ddy = py[jw]-py[i], ddz = pz[jw]-pz[i];
                    const float dd  = sqrtf(ddx*ddx + ddy*ddy + ddz*ddz);
                    const float inv = 1.f / fmaxf(dd, 1e-4f);
                    sdx[rr] = ddx*inv; sdy[rr] = ddy*inv; sdz[rr] = ddz*inv;
                }
            }
        }
        __syncthreads();

        // ---- MLP layer 1: hid[k][t] = silu(att_k*(p_i[t]+q_jk[t]) + bp1[t]) ----
        const float pv = g_p[(size_t)row*HID + t];
#pragma unroll
        for (int k = 0; k < KK; k++) {
            const float x = fmaf(satt[k], pv + g_q[(size_t)(bse + sidx[k])*HID + t], b1);
            hid[k][t] = x / (1.f + expf(-x));
        }
        __syncthreads();

        // ---- layer 2 matvec + directional output ----
        const int k = t >> 5, o = t & 31;
        float acc = bp2[o];
        const float4* hk4  = (const float4*)hid[k];
        const float*  wrow = &w2t[o*W2PAD];
#pragma unroll 16
        for (int q4 = 0; q4 < HID/4; q4++) {
            const float4 hv = hk4[q4];
            const float4 wv = *(const float4*)(wrow + q4*4);
            acc = fmaf(hv.x, wv.x, acc);
            acc = fmaf(hv.y, wv.y, acc);
            acc = fmaf(hv.z, wv.z, acc);
            acc = fmaf(hv.w, wv.w, acc);
        }
        const size_t ob = ((size_t)(row*KK + k)*OUTD + o) * 3;
        cout[ob+0] = acc * sdx[k];
        cout[ob+1] = acc * sdy[k];
        cout[ob+2] = acc * sdz[k];
        __syncthreads();   // protect shared reuse across ir iterations
    }
}

// ---------------------------------------------------------------------------
extern "C" void kernel_launch(void* const* d_in, const int* in_sizes, int n_in,
                              void* d_out, int out_size) {
    const int*   z   = (const int*)  d_in[0];
    const float* r   = (const float*)d_in[1];
    const float* h   = (const float*)d_in[2];
    const float* Wa  = (const float*)d_in[3];
    const float* ba  = (const float*)d_in[4];
    const float* Wp1 = (const float*)d_in[5];
    const float* bp1 = (const float*)d_in[6];
    const float* Wp2 = (const float*)d_in[7];
    const float* bp2 = (const float*)d_in[8];

    float* out = (float*)d_out;
    const int CSZ  = Nn*MA*KK*OUTD*3;         // 786432
    const int PREF = ROWS + ROWS*3;           // 4096 (z + r)
    const int has_prefix = (out_size == CSZ + PREF) ? 1 : 0;
    float* cout = has_prefix ? (out + PREF) : out;

    kA<<<ROWS/8, 256>>>(h, Wp1, Wa, z, r, out, has_prefix);
    kF<<<Nn*MA/4, 256>>>(z, r, ba, bp1, Wp2, bp2, cout);
}

// round 3
// speedup vs baseline: 1.5303x; 1.5303x over previous
#include <cuda_runtime.h>
#include <math.h>

#define Nn   4
#define MA   256
#define NFS  128
#define KK   8
#define HID  256
#define OUTD 32
#define RCf  5.0f
#define PIf  3.14159265358979323846f
#define ROWS (Nn*MA)   // 1024
#define HPAD 260       // padded hid row (floats); 260*4B = 1040B ≡ 16B-aligned

// ---------------- scratch ---------------------------------------------------
__device__ float g_a[ROWS];
__device__ float g_b[ROWS];
__device__ float g_p[ROWS*HID];
__device__ float g_q[ROWS*HID];

// ---------------- kernel A: per-atom projections (+ output prefix) ---------
// grid = 256 blocks, 256 threads, 4 rows per block.
__global__ void __launch_bounds__(256) kA(
        const float* __restrict__ h,
        const float* __restrict__ Wp1,
        const float* __restrict__ Wa,
        const int*   __restrict__ z,
        const float* __restrict__ r,
        float* __restrict__ out, int has_prefix) {
    __shared__ float hs[4*NFS];
    const int t = threadIdx.x;
    const int row0 = blockIdx.x * 4;
    for (int i = t; i < 4*NFS; i += 256) hs[i] = h[(size_t)row0*NFS + i];

    if (has_prefix) {
        const int gt = blockIdx.x * 256 + t;
        if (gt < ROWS)   out[gt] = (float)z[gt];
        if (gt < ROWS*3) out[ROWS + gt] = r[gt];
    }
    __syncthreads();

    float accp[4] = {0.f,0.f,0.f,0.f};
    float accq[4] = {0.f,0.f,0.f,0.f};

#pragma unroll 8
    for (int f = 0; f < NFS; f++) {
        const float wt = Wp1[f*HID + t];
        const float wb = Wp1[(NFS+f)*HID + t];
#pragma unroll
        for (int rr = 0; rr < 4; rr++) {
            const float hv = hs[rr*NFS + f];
            accp[rr] = fmaf(hv, wt, accp[rr]);
            accq[rr] = fmaf(hv, wb, accq[rr]);
        }
    }
#pragma unroll
    for (int rr = 0; rr < 4; rr++) {
        g_p[(size_t)(row0+rr)*HID + t] = accp[rr];
        g_q[(size_t)(row0+rr)*HID + t] = accq[rr];
    }

    // a,b dots: warps 0..3 handle rows 0..3
    const int w = t >> 5, lane = t & 31;
    if (w < 4) {
        float sa = 0.f, sb_ = 0.f;
        for (int f = lane; f < NFS; f += 32) {
            const float hv = hs[w*NFS + f];
            sa  = fmaf(hv, Wa[f],     sa);
            sb_ = fmaf(hv, Wa[NFS+f], sb_);
        }
#pragma unroll
        for (int off = 16; off; off >>= 1) {
            sa  += __shfl_down_sync(0xffffffffu, sa,  off);
            sb_ += __shfl_down_sync(0xffffffffu, sb_, off);
        }
        if (lane == 0) { g_a[row0+w] = sa; g_b[row0+w] = sb_; }
    }
}

// ---------------- kernel F: fused attention + topK + MLP + output ----------
// grid = 1024 (one block per row), 256 threads.
__global__ void __launch_bounds__(256) kF(
        const int*   __restrict__ z,
        const float* __restrict__ r,
        const float* __restrict__ ba_,
        const float* __restrict__ bp1,
        const float* __restrict__ Wp2,
        const float* __restrict__ bp2,
        float*       __restrict__ cout) {
    __shared__ float px[MA], py[MA], pz[MA], sbv[MA];
    __shared__ unsigned char smk[MA];
    __shared__ unsigned long long scand[64];
    __shared__ float wsum[8];
    __shared__ float satt[KK];
    __shared__ int   sidx[KK];
    __shared__ float sdx[KK], sdy[KK], sdz[KK];
    __shared__ __align__(16) float hid[KK][HPAD];
    __shared__ float sp[4*256];            // matvec partials

    const int t   = threadIdx.x;
    const int row = blockIdx.x;
    const int n   = row >> 8;
    const int i   = row & (MA-1);
    const int bse = n * MA;
    const int j   = t;

    px[j]  = r[(size_t)(bse+j)*3 + 0];
    py[j]  = r[(size_t)(bse+j)*3 + 1];
    pz[j]  = r[(size_t)(bse+j)*3 + 2];
    smk[j] = (z[bse+j] > -1) ? 1 : 0;
    sbv[j] = g_b[bse+j];
    const float b1  = bp1[t];
    const float bav = ba_[0];
    const float av  = g_a[row];
    __syncthreads();

    // ---- attention score ----
    const float dx = px[j]-px[i], dy = py[j]-py[i], dz = pz[j]-pz[i];
    const float d  = sqrtf(dx*dx + dy*dy + dz*dz);
    const bool  msk = smk[i] && smk[j] && (j != i);
    float g = 0.f;
    if (msk) {
        const float cf = 0.5f * (cosf(PIf * fminf(d, RCf) / RCf) + 1.f);
        g = expf(av + cf*sbv[j] + bav);
    }

    // ---- warp sums of g ----
    float s = g;
#pragma unroll
    for (int off = 16; off; off >>= 1) s += __shfl_xor_sync(0xffffffffu, s, off);
    if ((t & 31) == 0) wsum[t >> 5] = s;

    // ---- intra-warp exact full rank on unique u64 keys ----
    const unsigned long long key =
        (((unsigned long long)__float_as_uint(g)) << 32) | (unsigned)(MA-1-j);
    int rk = 0;
#pragma unroll
    for (int sft = 1; sft < 32; sft++) {
        const unsigned long long ok = __shfl_xor_sync(0xffffffffu, key, sft);
        rk += (ok > key);
    }
    if (rk < KK) scand[(t >> 5)*KK + rk] = key;
    __syncthreads();

    float sumg = 0.f;
#pragma unroll
    for (int w = 0; w < 8; w++) sumg += wsum[w];
    const float invsum = 1.f / fmaxf(sumg, 1e-8f);

    // ---- warp 0: rank the 64 candidates, emit global top-8 ----
    if (t < 32) {
        const unsigned long long k0 = scand[t], k1 = scand[t + 32];
        int r0 = 0, r1 = 0;
#pragma unroll 8
        for (int m = 0; m < 64; m++) {
            const unsigned long long km = scand[m];
            r0 += (km > k0);
            r1 += (km > k1);
        }
#pragma unroll
        for (int pick = 0; pick < 2; pick++) {
            const unsigned long long kk = pick ? k1 : k0;
            const int rr = pick ? r1 : r0;
            if (rr < KK) {
                const int jw = MA - 1 - (int)(kk & 0xffffffffu);
                satt[rr] = __uint_as_float((unsigned)(kk >> 32)) * invsum;
                sidx[rr] = jw;
                const float ddx = px[jw]-px[i], ddy = py[jw]-py[i], ddz = pz[jw]-pz[i];
                const float dd  = sqrtf(ddx*ddx + ddy*ddy + ddz*ddz);
                const float inv = 1.f / fmaxf(dd, 1e-4f);
                sdx[rr] = ddx*inv; sdy[rr] = ddy*inv; sdz[rr] = ddz*inv;
            }
        }
    }
    __syncthreads();

    // ---- MLP layer 1 ----
    const float pv = g_p[(size_t)row*HID + t];
#pragma unroll
    for (int k = 0; k < KK; k++) {
        const float x = fmaf(satt[k], pv + g_q[(size_t)(bse + sidx[k])*HID + t], b1);
        hid[k][t] = x / (1.f + expf(-x));   // silu
    }
    __syncthreads();

    // ---- layer 2 matvec: thread = (k, o-quad) x tt-quarter, 4 accumulators ----
    {
        const int task  = t & 63;          // 64 tasks: k(8) x oq(8)
        const int split = t >> 6;          // tt quarter
        const int k     = task >> 3;
        const int oq    = task & 7;
        float a0 = 0.f, a1 = 0.f, a2 = 0.f, a3 = 0.f;
        const float* hk = hid[k];
#pragma unroll
        for (int u = 0; u < 16; u++) {
            const int tt = split*64 + u*4;
            const float4 hv = *(const float4*)&hk[tt];
            const float4 w0 = __ldg((const float4*)&Wp2[(size_t)(tt+0)*OUTD + oq*4]);
            const float4 w1 = __ldg((const float4*)&Wp2[(size_t)(tt+1)*OUTD + oq*4]);
            const float4 w2 = __ldg((const float4*)&Wp2[(size_t)(tt+2)*OUTD + oq*4]);
            const float4 w3 = __ldg((const float4*)&Wp2[(size_t)(tt+3)*OUTD + oq*4]);
            a0 = fmaf(hv.x, w0.x, a0); a1 = fmaf(hv.x, w0.y, a1);
            a2 = fmaf(hv.x, w0.z, a2); a3 = fmaf(hv.x, w0.w, a3);
            a0 = fmaf(hv.y, w1.x, a0); a1 = fmaf(hv.y, w1.y, a1);
            a2 = fmaf(hv.y, w1.z, a2); a3 = fmaf(hv.y, w1.w, a3);
            a0 = fmaf(hv.z, w2.x, a0); a1 = fmaf(hv.z, w2.y, a1);
            a2 = fmaf(hv.z, w2.z, a2); a3 = fmaf(hv.z, w2.w, a3);
            a0 = fmaf(hv.w, w3.x, a0); a1 = fmaf(hv.w, w3.y, a1);
            a2 = fmaf(hv.w, w3.z, a2); a3 = fmaf(hv.w, w3.w, a3);
        }
        float4* spv = (float4*)&sp[split*256 + task*4];
        *spv = make_float4(a0, a1, a2, a3);
    }
    __syncthreads();

    // ---- finalize: sum 4 partials, apply bias + direction, store ----
    {
        const int task = t >> 2;           // k(8) x oq(8)
        const int oo   = t & 3;
        const int k    = task >> 3;
        const int o    = (task & 7)*4 + oo;
        const float acc = bp2[o] + sp[t] + sp[256 + t] + sp[512 + t] + sp[768 + t];
        const size_t ob = ((size_t)(row*KK + k)*OUTD + o) * 3;
        cout[ob+0] = acc * sdx[k];
        cout[ob+1] = acc * sdy[k];
        cout[ob+2] = acc * sdz[k];
    }
}

// ---------------------------------------------------------------------------
extern "C" void kernel_launch(void* const* d_in, const int* in_sizes, int n_in,
                              void* d_out, int out_size) {
    const int*   z   = (const int*)  d_in[0];
    const float* r   = (const float*)d_in[1];
    const float* h   = (const float*)d_in[2];
    const float* Wa  = (const float*)d_in[3];
    const float* ba  = (const float*)d_in[4];
    const float* Wp1 = (const float*)d_in[5];
    const float* bp1 = (const float*)d_in[6];
    const float* Wp2 = (const float*)d_in[7];
    const float* bp2 = (const float*)d_in[8];

    float* out = (float*)d_out;
    const int CSZ  = Nn*MA*KK*OUTD*3;         // 786432
    const int PREF = ROWS + ROWS*3;           // 4096 (z + r)
    const int has_prefix = (out_size == CSZ + PREF) ? 1 : 0;
    float* cout = has_prefix ? (out + PREF) : out;

    kA<<<ROWS/4, 256>>>(h, Wp1, Wa, z, r, out, has_prefix);
    kF<<<ROWS,   256>>>(z, r, ba, bp1, Wp2, bp2, cout);
}